// round 11
// baseline (speedup 1.0000x reference)
#include <cuda_runtime.h>
#include <math.h>

#define PI_D   3.141592653589793238462643383279
#define TWOPI_D 6.283185307179586476925286766559

// ---- problem sizes ----
#define NBATCH 128
#define K1N    100     // sum (2l+1), l<10
#define K2N    286     // sum (2l+1)^2, l<6
#define BI2    2560    // NBATCH * F1(20)

__constant__ int c_SQ[7] = {0,1,10,35,84,165,286}; // prefix of (2l+1)^2

// ---- tables (filled on device every call) ----
__device__ float  g_DM1[K1N*60];
__device__ float2 g_cY1[K1N*24];
__device__ float  g_d1tab[20*361*10];
__device__ float  g_DM2[K2N*20];
__device__ float2 g_cY2B[K2N*192];
__device__ float  g_d2tab[12*121*6];
__device__ float  g_w2j[12];

// ---- intermediates ----
__device__ float2 g_xb[19*60*NBATCH];
__device__ float2 g_X1[K1N*NBATCH];
__device__ float2 g_Yk1[20*K1N];
__device__ float2 g_bins[121*20*BI2];      // [ (m2+5)*11+(n2+5) ][ j ][ b*20+o ]
__device__ float2 g_X2[K2N*BI2];
__device__ float  g_K2T[192*800];
__device__ float2 g_Yk2[K2N*800];
__device__ float2 g_Z2[K2N*NBATCH*40];     // [t][b*40+o]
__device__ float  g_feat[NBATCH*40];

// ---------------------------------------------------------------------------
// Wigner-d (standard convention: d^l_{mp,m}(beta) = <l mp| e^{-i beta Jy} |l m>)
// ---------------------------------------------------------------------------
__device__ __forceinline__ double ipw(double x, int e){
    double r = 1.0;
    for (int i = 0; i < e; i++) r *= x;
    return r;
}
__device__ double wig_d(int l, int mp, int m, double beta){
    double fact[19];
    fact[0] = 1.0;
    for (int i = 1; i < 19; i++) fact[i] = fact[i-1] * (double)i;
    double cb = cos(0.5*beta), sb = sin(0.5*beta);
    int s0 = (m - mp > 0) ? (m - mp) : 0;
    int s1 = (l + m < l - mp) ? (l + m) : (l - mp);
    double pref = sqrt(fact[l+mp]*fact[l-mp]*fact[l+m]*fact[l-m]);
    double sum = 0.0;
    for (int s = s0; s <= s1; s++){
        double t = pref / (fact[l+m-s]*fact[s]*fact[mp-m+s]*fact[l-mp-s])
                 * ipw(cb, 2*l + m - mp - 2*s) * ipw(sb, mp - m + 2*s);
        if ((mp - m + s) & 1) t = -t;
        sum += t;
    }
    return sum;
}
__device__ __forceinline__ void decodeK2(int k, int &l, int &m, int &n){
    l = 0;
    while (k >= c_SQ[l+1]) l++;
    int r = k - c_SQ[l], L = 2*l + 1;
    m = r / L - l;
    n = r % L - l;
}

// ---------------------------------------------------------------------------
// Init kernels (tables, fp64 then cast — matches reference table precision)
// ---------------------------------------------------------------------------
__global__ void kInitDM1(){
    int k = blockIdx.x, j = threadIdx.x;            // k<100, j<60
    int l = (int)(sqrt((double)k) + 1e-9);
    int m = k - l*l - l;
    double beta = PI_D * (2*j + 1) / 120.0;
    double s = 0.0;
    for (int kk = 0; kk < 30; kk++) s += sin(beta*(2*kk+1)) / (2*kk+1);
    double w = (2.0/30.0) * sin(beta) * s;
    g_DM1[k*60 + j] = (float)(wig_d(l, m, 0, beta) * w);
}
__global__ void kInitY1(){                          // conj(Y1B)
    int k = blockIdx.x, g = threadIdx.x;            // g<24
    int l = (int)(sqrt((double)k) + 1e-9);
    int m = k - l*l - l;
    int bi = g / 8, ai = g % 8;
    double beta  = (bi + 1) * PI_D / 24.0;
    double alpha = TWOPI_D * ai / 8.0;
    double d = wig_d(l, m, 0, beta), ph = m * alpha; // conj -> +i m alpha
    g_cY1[k*24 + g] = make_float2((float)(d*cos(ph)), (float)(d*sin(ph)));
}
__global__ void kInitD1(){
    int p = blockIdx.x, j = blockIdx.y, l = threadIdx.x;   // p<361, j<20
    if (l >= 10) return;
    int m = p/19 - 9, n = p%19 - 9;
    float v = 0.f;
    if (l >= max(abs(m), abs(n))){
        double beta = PI_D * (2*j + 1) / 40.0;
        v = (float)((2*l + 1) * wig_d(l, m, n, beta));
    }
    g_d1tab[(j*361 + p)*10 + l] = v;
}
__global__ void kInitDM2(){
    int k = blockIdx.x, j = threadIdx.x;            // k<286, j<20
    int l, m, n; decodeK2(k, l, m, n);
    double beta = PI_D * (2*j + 1) / 40.0;
    double s = 0.0;
    for (int kk = 0; kk < 10; kk++) s += sin(beta*(2*kk+1)) / (2*kk+1);
    double w = (2.0/10.0) * sin(beta) * s;
    g_DM2[k*20 + j] = (float)(w * wig_d(l, m, n, beta));
}
__global__ void kInitY2B(){                         // conj(Y2B)
    int k = blockIdx.x, g = threadIdx.x;            // g<192
    int l, m, n; decodeK2(k, l, m, n);
    int bi = g / 64, ai = (g / 8) % 8, ci = g % 8;
    double beta  = (bi + 1) * PI_D / 24.0;
    double alpha = TWOPI_D * ai / 8.0;
    double gamma = (-TWOPI_D + (PI_D/2.0)*ci) - alpha;
    double d = wig_d(l, m, n, beta);
    double ph = m*alpha + n*gamma;                  // conj -> +i(m a + n g)
    g_cY2B[k*192 + g] = make_float2((float)(d*cos(ph)), (float)(d*sin(ph)));
}
__global__ void kInitD2(){
    int p = blockIdx.x, j = blockIdx.y, l = threadIdx.x;   // p<121, j<12
    if (l >= 6) return;
    int m = p/11 - 5, n = p%11 - 5;
    float v = 0.f;
    if (l >= max(abs(m), abs(n))){
        double beta = PI_D * (2*j + 1) / 24.0;
        v = (float)((2*l + 1) * wig_d(l, m, n, beta));
    }
    g_d2tab[(j*121 + p)*6 + l] = v;
}
__global__ void kInitW2(){
    int j = threadIdx.x;
    if (j >= 12) return;
    double beta = PI_D * (2*j + 1) / 24.0;
    double s = 0.0;
    for (int kk = 0; kk < 6; kk++) s += sin(beta*(2*kk+1)) / (2*kk+1);
    g_w2j[j] = (float)((2.0/6.0) * sin(beta) * s);
}

// ---------------------------------------------------------------------------
// Stage kernels
// ---------------------------------------------------------------------------
// alpha-DFT of input: xb[mi][j][b] = (1/60) sum_a x[b,j,a] e^{-i m alpha_a}
__global__ void kDFT1(const float* __restrict__ x){
    __shared__ float2 tw[60];
    int j = blockIdx.x, mi = blockIdx.y, t = threadIdx.x;  // t = batch
    int m = mi - 9;
    if (t < 60){
        float ang = -(float)m * (6.28318530717958647f/60.f) * (float)t;
        float s, c; sincosf(ang, &s, &c);
        tw[t] = make_float2(c, s);
    }
    __syncthreads();
    const float* row = x + t*3600 + j*60;
    float2 acc = make_float2(0.f, 0.f);
    #pragma unroll 4
    for (int a = 0; a < 60; a++){
        float v = row[a];
        acc.x += v * tw[a].x;
        acc.y += v * tw[a].y;
    }
    acc.x *= (1.f/60.f); acc.y *= (1.f/60.f);
    g_xb[(mi*60 + j)*NBATCH + t] = acc;
}

// X1[k][b] = sum_j DM1[k][j] * xb[m(k)][j][b]
__global__ void kX1(){
    int k = blockIdx.x, b = threadIdx.x;
    int l = (int)(sqrt((double)k) + 1e-9);
    int mi = (k - l*l - l) + 9;
    float2 acc = make_float2(0.f, 0.f);
    for (int j = 0; j < 60; j++){
        float d = g_DM1[k*60 + j];
        float2 v = g_xb[(mi*60 + j)*NBATCH + b];
        acc.x += d * v.x; acc.y += d * v.y;
    }
    g_X1[k*NBATCH + b] = acc;
}

// conj(Yk1)[o][k] = SC1 * sum_g cY1[k][g] * kernel1[0,o,g]
__global__ void kYk1(const float* __restrict__ k1){
    int o = blockIdx.x, k = threadIdx.x;
    if (k >= K1N) return;
    float2 acc = make_float2(0.f, 0.f);
    for (int g = 0; g < 24; g++){
        float w = k1[o*24 + g];
        float2 y = g_cY1[k*24 + g];
        acc.x += w * y.x; acc.y += w * y.y;
    }
    float sc = rsqrtf(24.0f);
    g_Yk1[o*K1N + k] = make_float2(acc.x*sc, acc.y*sc);
}

// Fused layer-1 synthesis + relu + layer-2 fft2 bins. One block per (o,b).
__global__ void kSynth1(){
    __shared__ float2 XL[100], YL[100], E[380], prod[3610], G[361], H[380], T2[220];
    __shared__ float  GR[400];
    int o = blockIdx.x, b = blockIdx.y, tid = threadIdx.x;

    for (int p = tid; p < 100; p += 256){
        XL[p] = g_X1[p*NBATCH + b];
        YL[p] = g_Yk1[o*K1N + p];
    }
    for (int p = tid; p < 380; p += 256){
        int mi = p / 20, a = p % 20;
        float ang = (float)(mi - 9) * (6.28318530717958647f/20.f) * (float)a;
        float s, c; sincosf(ang, &s, &c);
        E[p] = make_float2(c, s);   // e^{ i(mi-9) alpha_a }
    }
    __syncthreads();
    for (int p = tid; p < 361; p += 256){
        int m = p/19 - 9, n = p%19 - 9;
        int lmin = max(abs(m), abs(n));
        for (int l = lmin; l < 10; l++){
            float2 xa = XL[l*l + m + l], ya = YL[l*l + n + l];
            prod[p*10 + l] = make_float2(xa.x*ya.x - xa.y*ya.y, xa.x*ya.y + xa.y*ya.x);
        }
    }
    __syncthreads();

    for (int j = 0; j < 20; j++){
        // G[m,n] = sum_l (2l+1) d^l_{mn}(b1_j) * X_m Y_n
        for (int p = tid; p < 361; p += 256){
            int m = p/19 - 9, n = p%19 - 9;
            int lmin = max(abs(m), abs(n));
            float2 acc = make_float2(0.f, 0.f);
            const float* dt = &g_d1tab[(j*361 + p)*10];
            for (int l = lmin; l < 10; l++){
                float d = dt[l];
                float2 pr = prod[p*10 + l];
                acc.x += d * pr.x; acc.y += d * pr.y;
            }
            G[p] = acc;
        }
        __syncthreads();
        // H[m][a3] = sum_n G e^{i n alpha3}
        for (int p = tid; p < 380; p += 256){
            int mi = p / 20, a3 = p % 20;
            float2 acc = make_float2(0.f, 0.f);
            #pragma unroll
            for (int ni = 0; ni < 19; ni++){
                float2 g = G[mi*19 + ni], e = E[ni*20 + a3];
                acc.x += g.x*e.x - g.y*e.y;
                acc.y += g.x*e.y + g.y*e.x;
            }
            H[p] = acc;
        }
        __syncthreads();
        // grid + relu
        for (int p = tid; p < 400; p += 256){
            int a2 = p / 20, a3 = p % 20;
            float v = 0.f;
            #pragma unroll
            for (int mi = 0; mi < 19; mi++){
                float2 h = H[mi*20 + a3], e = E[mi*20 + a2];
                v += h.x*e.x - h.y*e.y;
            }
            GR[p] = fmaxf(v, 0.f);
        }
        __syncthreads();
        // t[n2][a2] = sum_a3 grid * e^{-i n2 alpha3}
        for (int p = tid; p < 220; p += 256){
            int ni2 = p / 20, a2 = p % 20;
            float2 acc = make_float2(0.f, 0.f);
            int row = (14 - ni2) * 20;      // index of m = -n2
            for (int a3 = 0; a3 < 20; a3++){
                float g = GR[a2*20 + a3];
                float2 e = E[row + a3];
                acc.x += g * e.x; acc.y += g * e.y;
            }
            T2[p] = acc;
        }
        __syncthreads();
        // bins[m2][n2] = (1/400) sum_a2 t * e^{-i m2 alpha2}
        for (int p = tid; p < 121; p += 256){
            int mi2 = p / 11, ni2 = p % 11;
            float2 acc = make_float2(0.f, 0.f);
            int row = (14 - mi2) * 20;
            for (int a2 = 0; a2 < 20; a2++){
                float2 t = T2[ni2*20 + a2], e = E[row + a2];
                acc.x += t.x*e.x - t.y*e.y;
                acc.y += t.x*e.y + t.y*e.x;
            }
            acc.x *= (1.f/400.f); acc.y *= (1.f/400.f);
            g_bins[(p*20 + j)*BI2 + b*20 + o] = acc;
        }
        __syncthreads();
    }
}

__global__ void kK2T(const float* __restrict__ k2){
    int id = blockIdx.x*128 + threadIdx.x;
    if (id < 153600){
        int io = id / 192, g = id % 192;
        g_K2T[g*800 + io] = k2[id];
    }
}

// conj(Yk2)[k][io] = SC2 * sum_g cY2B[k][g] * kernel2[io][g]
__global__ void kYk2(){
    __shared__ float2 Ys[4*192];
    int tid = threadIdx.x;
    int io = blockIdx.y*128 + tid;
    for (int idx = tid; idx < 768; idx += 128){
        int q = idx / 192, g = idx % 192;
        int kk = blockIdx.x*4 + q;
        Ys[idx] = (kk < K2N) ? g_cY2B[kk*192 + g] : make_float2(0.f, 0.f);
    }
    __syncthreads();
    if (io >= 800) return;
    float2 acc[4] = {{0,0},{0,0},{0,0},{0,0}};
    for (int g = 0; g < 192; g++){
        float kv = g_K2T[g*800 + io];
        #pragma unroll
        for (int q = 0; q < 4; q++){
            acc[q].x += Ys[q*192 + g].x * kv;
            acc[q].y += Ys[q*192 + g].y * kv;
        }
    }
    float sc = rsqrtf(3840.0f);
    #pragma unroll
    for (int q = 0; q < 4; q++){
        int kk = blockIdx.x*4 + q;
        if (kk < K2N) g_Yk2[kk*800 + io] = make_float2(acc[q].x*sc, acc[q].y*sc);
    }
}

// X2[k][bi] = sum_j DM2[k][j] * bins[p(k)][j][bi]
__global__ void kX2(){
    int k = blockIdx.x;
    int bi = blockIdx.y*128 + threadIdx.x;
    int l, m, n; decodeK2(k, l, m, n);
    int p = (m + 5)*11 + (n + 5);
    float2 acc = make_float2(0.f, 0.f);
    for (int j = 0; j < 20; j++){
        float d = g_DM2[k*20 + j];
        float2 v = g_bins[(p*20 + j)*BI2 + bi];
        acc.x += d * v.x; acc.y += d * v.y;
    }
    g_X2[k*BI2 + bi] = acc;
}

// Z[m,n,b,o] = sum_{kk,i} X2[(l,m,kk)][b,i] * cYk2[(l,n,kk)][i,o]   (per l)
template<int L>
__global__ void kZ2(){
    const int l = (L - 1) / 2;
    const int base = c_SQ[l];
    int b = blockIdx.x, tid = threadIdx.x;
    __shared__ float2 A[L*L*20];
    for (int idx = tid; idx < L*L*20; idx += 256){
        int m = idx / (L*20), r = idx % (L*20), kk = r / 20, i = r % 20;
        A[idx] = g_X2[(base + m*L + kk)*BI2 + b*20 + i];
    }
    __syncthreads();
    for (int p = tid; p < L*40; p += 256){
        int n = p / 40, o = p % 40;
        float2 acc[L];
        #pragma unroll
        for (int m = 0; m < L; m++) acc[m] = make_float2(0.f, 0.f);
        for (int kk = 0; kk < L; kk++){
            const float2* Yrow = &g_Yk2[(base + n*L + kk)*800 + o];
            #pragma unroll 4
            for (int i = 0; i < 20; i++){
                float2 y = Yrow[i*40];
                #pragma unroll
                for (int m = 0; m < L; m++){
                    float2 a = A[m*L*20 + kk*20 + i];
                    acc[m].x += a.x*y.x - a.y*y.y;
                    acc[m].y += a.x*y.y + a.y*y.x;
                }
            }
        }
        #pragma unroll
        for (int m = 0; m < L; m++)
            g_Z2[(base + m*L + n)*5120 + b*40 + o] = acc[m];
    }
}

// Fused layer-2 synthesis + relu + beta-quadrature + feature. Block per (o,b).
__global__ void kSynth2(){
    __shared__ float2 ZL[286], E2[132], G2[121], H2[132];
    __shared__ float  red[128];
    int o = blockIdx.x, b = blockIdx.y, tid = threadIdx.x;
    for (int t = tid; t < 286; t += 128) ZL[t] = g_Z2[t*5120 + b*40 + o];
    for (int p = tid; p < 132; p += 128){
        int mi = p / 12, a = p % 12;
        float ang = (float)(mi - 5) * (6.28318530717958647f/12.f) * (float)a;
        float s, c; sincosf(ang, &s, &c);
        E2[p] = make_float2(c, s);
    }
    __syncthreads();
    float facc = 0.f;
    for (int j = 0; j < 12; j++){
        for (int p = tid; p < 121; p += 128){
            int m = p/11 - 5, n = p%11 - 5;
            int lmin = max(abs(m), abs(n));
            float2 acc = make_float2(0.f, 0.f);
            const float* dt = &g_d2tab[(j*121 + p)*6];
            for (int l = lmin; l < 6; l++){
                int Ls = 2*l + 1;
                float2 z = ZL[c_SQ[l] + (m + l)*Ls + (n + l)];
                float d = dt[l];
                acc.x += d * z.x; acc.y += d * z.y;
            }
            G2[p] = acc;
        }
        __syncthreads();
        for (int p = tid; p < 132; p += 128){
            int mi = p / 12, a3 = p % 12;
            float2 acc = make_float2(0.f, 0.f);
            #pragma unroll
            for (int ni = 0; ni < 11; ni++){
                float2 g = G2[mi*11 + ni], e = E2[ni*12 + a3];
                acc.x += g.x*e.x - g.y*e.y;
                acc.y += g.x*e.y + g.y*e.x;
            }
            H2[p] = acc;
        }
        __syncthreads();
        float wj = g_w2j[j];
        for (int p = tid; p < 144; p += 128){
            int a2 = p / 12, a3 = p % 12;
            float v = 0.f;
            #pragma unroll
            for (int mi = 0; mi < 11; mi++){
                float2 h = H2[mi*12 + a3], e = E2[mi*12 + a2];
                v += h.x*e.x - h.y*e.y;
            }
            facc += wj * fmaxf(v, 0.f);
        }
        __syncthreads();
    }
    red[tid] = facc;
    __syncthreads();
    for (int s = 64; s > 0; s >>= 1){
        if (tid < s) red[tid] += red[tid + s];
        __syncthreads();
    }
    if (tid == 0){
        const float INTEG = (float)((TWOPI_D/12.0)*(TWOPI_D/12.0));
        g_feat[b*40 + o] = INTEG * red[0];
    }
}

__global__ void kOut(const float* __restrict__ wout, const float* __restrict__ bias,
                     float* __restrict__ out){
    int g = blockIdx.x*128 + threadIdx.x;
    if (g >= 1280) return;
    int b = g / 10, fo = g % 10;
    float s = bias[fo];
    #pragma unroll
    for (int o = 0; o < 40; o++) s += g_feat[b*40 + o] * wout[fo*40 + o];
    out[g] = s;
}

// ---------------------------------------------------------------------------
extern "C" void kernel_launch(void* const* d_in, const int* in_sizes, int n_in,
                              void* d_out, int out_size){
    (void)in_sizes; (void)n_in; (void)out_size;
    const float* x  = (const float*)d_in[0];
    const float* k1 = (const float*)d_in[1];
    const float* k2 = (const float*)d_in[2];
    const float* wo = (const float*)d_in[3];
    const float* bo = (const float*)d_in[4];
    float* out = (float*)d_out;

    kInitDM1<<<100, 60>>>();
    kInitY1 <<<100, 24>>>();
    kInitD1 <<<dim3(361, 20), 16>>>();
    kInitDM2<<<286, 20>>>();
    kInitY2B<<<286, 192>>>();
    kInitD2 <<<dim3(121, 12), 8>>>();
    kInitW2 <<<1, 32>>>();

    kDFT1  <<<dim3(60, 19), 128>>>(x);
    kX1    <<<100, 128>>>();
    kYk1   <<<20, 128>>>(k1);
    kSynth1<<<dim3(20, 128), 256>>>();

    kK2T   <<<1200, 128>>>(k2);
    kYk2   <<<dim3(72, 7), 128>>>();
    kX2    <<<dim3(286, 20), 128>>>();

    kZ2<1> <<<128, 256>>>();
    kZ2<3> <<<128, 256>>>();
    kZ2<5> <<<128, 256>>>();
    kZ2<7> <<<128, 256>>>();
    kZ2<9> <<<128, 256>>>();
    kZ2<11><<<128, 256>>>();

    kSynth2<<<dim3(40, 128), 128>>>();
    kOut   <<<10, 128>>>(wo, bo, out);
}

// round 12
// speedup vs baseline: 1.5555x; 1.5555x over previous
#include <cuda_runtime.h>
#include <math.h>

#define PI_D    3.141592653589793238462643383279
#define TWOPI_D 6.283185307179586476925286766559

// ---- problem sizes ----
#define NBATCH 128
#define K1N    100     // sum (2l+1), l<10
#define K2N    286     // sum (2l+1)^2, l<6
#define BI2    2560    // NBATCH * F1(20)

__constant__ int c_SQ[7]    = {0,1,10,35,84,165,286};                 // prefix (2l+1)^2, l<6
__constant__ int c_SQ10[11] = {0,1,10,35,84,165,286,455,680,969,1330};// prefix l<10

__constant__ double c_fact[19] = {
    1.0,1.0,2.0,6.0,24.0,120.0,720.0,5040.0,40320.0,362880.0,
    3628800.0,39916800.0,479001600.0,6227020800.0,87178291200.0,
    1307674368000.0,20922789888000.0,355687428096000.0,6402373705728000.0};
__constant__ double c_rfact[19] = {
    1.0,1.0,1.0/2.0,1.0/6.0,1.0/24.0,1.0/120.0,1.0/720.0,1.0/5040.0,
    1.0/40320.0,1.0/362880.0,1.0/3628800.0,1.0/39916800.0,1.0/479001600.0,
    1.0/6227020800.0,1.0/87178291200.0,1.0/1307674368000.0,
    1.0/20922789888000.0,1.0/355687428096000.0,1.0/6402373705728000.0};

// ---- raw wigner tables (dedup) ----
__device__ float g_dB1[20*1330];   // d^l_{mn}(beta1_j), l<10 full
__device__ float g_dS2[3*286];     // d^l_{mn}(s2 betas), l<6 full
__device__ float g_dS2m0[3*100];   // d^l_{m0}(s2 betas), l<10
__device__ float g_dB2[12*286];    // d^l_{mn}(beta2_j), l<6 full
__device__ float g_dBm0[60*100];   // d^l_{m0}(beta_in_j), l<10
__device__ float g_win[60], g_w1[20], g_w2j[12];

// ---- assembled tables ----
__device__ float  g_DM1[K1N*60];
__device__ float2 g_cY1[K1N*24];
__device__ float  g_d1tab[20*361*10];
__device__ float  g_DM2[K2N*20];
__device__ float2 g_cY2B[K2N*192];
__device__ float  g_d2tab[12*121*6];
__device__ float2 g_E1[380];   // e^{i(mi-9)*2pi*a/20}, mi<19, a<20
__device__ float2 g_E2[132];   // e^{i(mi-5)*2pi*a/12}, mi<11, a<12

// ---- intermediates ----
__device__ float2 g_xb[19*60*NBATCH];
__device__ float2 g_X1[K1N*NBATCH];
__device__ float2 g_Yk1[20*K1N];
__device__ float2 g_bins[121*20*BI2];      // [p2][j][b*20+o]
__device__ float2 g_X2[K2N*BI2];
__device__ float  g_K2T[192*800];
__device__ float2 g_Yk2[K2N*800];
__device__ float2 g_Z2[K2N*NBATCH*40];
__device__ float  g_feat[NBATCH*40];

// ---------------------------------------------------------------------------
// Fast Wigner-d: d^l_{mp,m}(beta) = <l mp| e^{-i beta Jy} |l m>
// explicit factorial sum, powers updated incrementally.
// ---------------------------------------------------------------------------
__device__ double wig_fast(int l, int mp, int m, double beta){
    double cb = cos(0.5*beta), sb = sin(0.5*beta);
    int s0 = (m - mp > 0) ? (m - mp) : 0;
    int s1 = (l + m < l - mp) ? (l + m) : (l - mp);
    if (s1 < s0) return 0.0;
    double pref = sqrt(c_fact[l+mp]*c_fact[l-mp]*c_fact[l+m]*c_fact[l-m]);
    int ec = 2*l + m - mp - 2*s0, es = mp - m + 2*s0;
    double pw = 1.0;
    for (int i = 0; i < ec; i++) pw *= cb;
    for (int i = 0; i < es; i++) pw *= sb;
    double ratio = (sb*sb)/(cb*cb);
    double sum = 0.0;
    for (int s = s0; s <= s1; s++){
        double t = c_rfact[l+m-s]*c_rfact[s]*c_rfact[mp-m+s]*c_rfact[l-mp-s]*pw;
        sum += ((mp - m + s) & 1) ? -t : t;
        pw *= ratio;
    }
    return pref * sum;
}
__device__ __forceinline__ void decode6(int k, int &l, int &m, int &n){
    l = 0; while (k >= c_SQ[l+1]) l++;
    int r = k - c_SQ[l], L = 2*l+1; m = r/L - l; n = r%L - l;
}
__device__ __forceinline__ void decode10(int k, int &l, int &m, int &n){
    l = 0; while (k >= c_SQ10[l+1]) l++;
    int r = k - c_SQ10[l], L = 2*l+1; m = r/L - l; n = r%L - l;
}

// ---------------------------------------------------------------------------
// Init: quadrature weights
// ---------------------------------------------------------------------------
__global__ void kWeights(){
    int t = threadIdx.x;
    if (t < 60){
        double beta = PI_D*(2*t+1)/120.0, s = 0.0;
        for (int k = 0; k < 30; k++) s += sin(beta*(2*k+1))/(2*k+1);
        g_win[t] = (float)((2.0/30.0)*sin(beta)*s);
    } else if (t < 80){
        int j = t - 60;
        double beta = PI_D*(2*j+1)/40.0, s = 0.0;
        for (int k = 0; k < 10; k++) s += sin(beta*(2*k+1))/(2*k+1);
        g_w1[j] = (float)((2.0/10.0)*sin(beta)*s);
    } else if (t < 92){
        int j = t - 80;
        double beta = PI_D*(2*j+1)/24.0, s = 0.0;
        for (int k = 0; k < 6; k++) s += sin(beta*(2*k+1))/(2*k+1);
        g_w2j[j] = (float)((2.0/6.0)*sin(beta)*s);
    }
}

// Raw wigner evals, deduped: 37190 total
__global__ void kRawAll(){
    int id = blockIdx.x*256 + threadIdx.x;
    if (id < 26600){                 // dB1: j<20, k<1330
        int j = id/1330, k = id%1330, l, m, n; decode10(k, l, m, n);
        g_dB1[id] = (float)wig_fast(l, m, n, PI_D*(2*j+1)/40.0);
    } else if (id < 27458){          // dS2: bi<3, k<286
        int r = id - 26600, bi = r/286, k = r%286, l, m, n; decode6(k, l, m, n);
        g_dS2[r] = (float)wig_fast(l, m, n, (bi+1)*PI_D/24.0);
    } else if (id < 27758){          // dS2m0: bi<3, k<100
        int r = id - 27458, bi = r/100, k = r%100;
        int l = (int)(sqrt((double)k)+1e-9), m = k - l*l - l;
        g_dS2m0[r] = (float)wig_fast(l, m, 0, (bi+1)*PI_D/24.0);
    } else if (id < 31190){          // dB2: j<12, k<286
        int r = id - 27758, j = r/286, k = r%286, l, m, n; decode6(k, l, m, n);
        g_dB2[r] = (float)wig_fast(l, m, n, PI_D*(2*j+1)/24.0);
    } else if (id < 37190){          // dBm0: j<60, k<100
        int r = id - 31190, j = r/100, k = r%100;
        int l = (int)(sqrt((double)k)+1e-9), m = k - l*l - l;
        g_dBm0[r] = (float)wig_fast(l, m, 0, PI_D*(2*j+1)/120.0);
    }
}

// Assemble all final tables from raw ones: 150456 elements
__global__ void kAsmAll(){
    int id = blockIdx.x*256 + threadIdx.x;
    if (id < 6000){                                  // DM1[k*60+j]
        int k = id/60, j = id%60;
        g_DM1[id] = g_dBm0[j*100 + k] * g_win[j];
    } else if (id < 8400){                           // cY1[k*24+g]
        int r = id - 6000, k = r/24, g = r%24;
        int l = (int)(sqrt((double)k)+1e-9), m = k - l*l - l;
        int bi = g/8, ai = g%8;
        double d = (double)g_dS2m0[bi*100 + k];
        double ph = (double)m * (TWOPI_D*ai/8.0);    // conj -> +i m alpha
        double s, c; sincos(ph, &s, &c);
        g_cY1[r] = make_float2((float)(d*c), (float)(d*s));
    } else if (id < 80600){                          // d1tab[(j*361+p)*10+l]
        int r = id - 8400;
        int l = r%10, q = r/10, p = q%361, j = q/361;
        int m = p/19 - 9, n = p%19 - 9;
        float v = 0.f;
        if (l >= max(abs(m), abs(n)))
            v = (float)(2*l+1) * g_dB1[j*1330 + c_SQ10[l] + (m+l)*(2*l+1) + (n+l)];
        g_d1tab[r] = v;
    } else if (id < 86320){                          // DM2[k*20+j]
        int r = id - 80600, k = r/20, j = r%20;
        g_DM2[r] = g_w1[j] * g_dB1[j*1330 + k];
    } else if (id < 141232){                         // cY2B[k*192+g]
        int r = id - 86320, k = r/192, g = r%192;
        int l, m, n; decode6(k, l, m, n);
        int bi = g/64, ai = (g/8)%8, ci = g%8;
        double alpha = TWOPI_D*ai/8.0;
        double gamma = (-TWOPI_D + (PI_D/2.0)*ci) - alpha;
        double d = (double)g_dS2[bi*286 + k];
        double ph = m*alpha + n*gamma;               // conj -> +i
        double s, c; sincos(ph, &s, &c);
        g_cY2B[r] = make_float2((float)(d*c), (float)(d*s));
    } else if (id < 149944){                         // d2tab[(j*121+p)*6+l]
        int r = id - 141232;
        int l = r%6, q = r/6, p = q%121, j = q/121;
        int m = p/11 - 5, n = p%11 - 5;
        float v = 0.f;
        if (l >= max(abs(m), abs(n)))
            v = (float)(2*l+1) * g_dB2[j*286 + c_SQ[l] + (m+l)*(2*l+1) + (n+l)];
        g_d2tab[r] = v;
    } else if (id < 150324){                         // E1[380]
        int r = id - 149944, mi = r/20, a = r%20;
        double ang = (double)(mi-9) * (TWOPI_D/20.0) * a;
        double s, c; sincos(ang, &s, &c);
        g_E1[r] = make_float2((float)c, (float)s);
    } else if (id < 150456){                         // E2[132]
        int r = id - 150324, mi = r/12, a = r%12;
        double ang = (double)(mi-5) * (TWOPI_D/12.0) * a;
        double s, c; sincos(ang, &s, &c);
        g_E2[r] = make_float2((float)c, (float)s);
    }
}

// ---------------------------------------------------------------------------
// Stage kernels
// ---------------------------------------------------------------------------
__global__ void kDFT1(const float* __restrict__ x){
    __shared__ float2 tw[60];
    int j = blockIdx.x, mi = blockIdx.y, t = threadIdx.x;
    int m = mi - 9;
    if (t < 60){
        float ang = -(float)m * (6.28318530717958647f/60.f) * (float)t;
        float s, c; sincosf(ang, &s, &c);
        tw[t] = make_float2(c, s);
    }
    __syncthreads();
    const float* row = x + t*3600 + j*60;
    float2 acc = make_float2(0.f, 0.f);
    #pragma unroll 4
    for (int a = 0; a < 60; a++){
        float v = row[a];
        acc.x += v * tw[a].x;
        acc.y += v * tw[a].y;
    }
    acc.x *= (1.f/60.f); acc.y *= (1.f/60.f);
    g_xb[(mi*60 + j)*NBATCH + t] = acc;
}

__global__ void kX1(){
    int k = blockIdx.x, b = threadIdx.x;
    int l = (int)(sqrt((double)k) + 1e-9);
    int mi = (k - l*l - l) + 9;
    float2 acc = make_float2(0.f, 0.f);
    for (int j = 0; j < 60; j++){
        float d = g_DM1[k*60 + j];
        float2 v = g_xb[(mi*60 + j)*NBATCH + b];
        acc.x += d * v.x; acc.y += d * v.y;
    }
    g_X1[k*NBATCH + b] = acc;
}

__global__ void kYk1(const float* __restrict__ k1){
    int o = blockIdx.x, k = threadIdx.x;
    if (k >= K1N) return;
    float2 acc = make_float2(0.f, 0.f);
    for (int g = 0; g < 24; g++){
        float w = k1[o*24 + g];
        float2 y = g_cY1[k*24 + g];
        acc.x += w * y.x; acc.y += w * y.y;
    }
    float sc = rsqrtf(24.0f);
    g_Yk1[o*K1N + k] = make_float2(acc.x*sc, acc.y*sc);
}

// Fused layer-1 synthesis + relu + layer-2 fft2 bins, Hermitian-halved.
__global__ void kSynth1(){
    __shared__ float2 XL[100], YL[100], E[380], prod[1810], G[361], H[200], T2[220];
    __shared__ float  GR[400];
    int o = blockIdx.x, b = blockIdx.y, tid = threadIdx.x;

    for (int p = tid; p < 100; p += 256){
        XL[p] = g_X1[p*NBATCH + b];
        YL[p] = g_Yk1[o*K1N + p];
    }
    for (int p = tid; p < 380; p += 256) E[p] = g_E1[p];
    __syncthreads();
    // products for half of (m,n) plane (p<=180)
    for (int p = tid; p < 181; p += 256){
        int m = p/19 - 9, n = p%19 - 9;
        int lmin = max(abs(m), abs(n));
        for (int l = lmin; l < 10; l++){
            float2 xa = XL[l*l + m + l], ya = YL[l*l + n + l];
            prod[p*10 + l] = make_float2(xa.x*ya.x - xa.y*ya.y, xa.x*ya.y + xa.y*ya.x);
        }
    }
    __syncthreads();

    for (int j = 0; j < 20; j++){
        // G[m,n], half + conj mirror (G[-m,-n] = conj G[m,n])
        for (int p = tid; p < 181; p += 256){
            int m = p/19 - 9, n = p%19 - 9;
            int lmin = max(abs(m), abs(n));
            float2 acc = make_float2(0.f, 0.f);
            const float* dt = &g_d1tab[(j*361 + p)*10];
            for (int l = lmin; l < 10; l++){
                float d = dt[l];
                float2 pr = prod[p*10 + l];
                acc.x += d * pr.x; acc.y += d * pr.y;
            }
            G[p] = acc;
            G[360 - p] = make_float2(acc.x, -acc.y);
        }
        __syncthreads();
        // H[m][a3], only m<=0 rows (mi 0..9); H_{-m}[a3] = conj(H_m[a3])
        for (int p = tid; p < 200; p += 256){
            int mi = p / 20, a3 = p % 20;
            float2 acc = make_float2(0.f, 0.f);
            #pragma unroll
            for (int ni = 0; ni < 19; ni++){
                float2 g = G[mi*19 + ni], e = E[ni*20 + a3];
                acc.x += g.x*e.x - g.y*e.y;
                acc.y += g.x*e.y + g.y*e.x;
            }
            H[p] = acc;
        }
        __syncthreads();
        // grid + relu, pair-sum: v = Re(H_0) + 2 sum_{m<0} Re(H_m e^{im a2})
        for (int p = tid; p < 400; p += 256){
            int a2 = p / 20, a3 = p % 20;
            float v = H[9*20 + a3].x;
            #pragma unroll
            for (int mi = 0; mi < 9; mi++){
                float2 h = H[mi*20 + a3], e = E[mi*20 + a2];
                v += 2.f * (h.x*e.x - h.y*e.y);
            }
            GR[p] = fmaxf(v, 0.f);
        }
        __syncthreads();
        // t[n2][a2]: compute n2>=0 rows, mirror t[-n2] = conj(t[n2])
        for (int p = tid; p < 120; p += 256){
            int ni2 = 5 + p/20, a2 = p%20;
            float2 acc = make_float2(0.f, 0.f);
            int row = (14 - ni2) * 20;
            for (int a3 = 0; a3 < 20; a3++){
                float g = GR[a2*20 + a3];
                float2 e = E[row + a3];
                acc.x += g * e.x; acc.y += g * e.y;
            }
            T2[ni2*20 + a2] = acc;
            if (ni2 > 5) T2[(10 - ni2)*20 + a2] = make_float2(acc.x, -acc.y);
        }
        __syncthreads();
        // bins: compute p2<=60, mirror bins[120-p2] = conj
        for (int p = tid; p < 61; p += 256){
            int mi2 = p / 11, ni2 = p % 11;
            float2 acc = make_float2(0.f, 0.f);
            int row = (14 - mi2) * 20;
            for (int a2 = 0; a2 < 20; a2++){
                float2 t = T2[ni2*20 + a2], e = E[row + a2];
                acc.x += t.x*e.x - t.y*e.y;
                acc.y += t.x*e.y + t.y*e.x;
            }
            acc.x *= (1.f/400.f); acc.y *= (1.f/400.f);
            g_bins[(p*20 + j)*BI2 + b*20 + o] = acc;
            if (p < 60)
                g_bins[((120 - p)*20 + j)*BI2 + b*20 + o] = make_float2(acc.x, -acc.y);
        }
        __syncthreads();
    }
}

__global__ void kK2T(const float* __restrict__ k2){
    int id = blockIdx.x*128 + threadIdx.x;
    if (id < 153600){
        int io = id / 192, g = id % 192;
        g_K2T[g*800 + io] = k2[id];
    }
}

__global__ void kYk2(){
    __shared__ float2 Ys[4*192];
    int tid = threadIdx.x;
    int io = blockIdx.y*128 + tid;
    for (int idx = tid; idx < 768; idx += 128){
        int q = idx / 192, g = idx % 192;
        int kk = blockIdx.x*4 + q;
        Ys[idx] = (kk < K2N) ? g_cY2B[kk*192 + g] : make_float2(0.f, 0.f);
    }
    __syncthreads();
    if (io >= 800) return;
    float2 acc[4] = {{0,0},{0,0},{0,0},{0,0}};
    for (int g = 0; g < 192; g++){
        float kv = g_K2T[g*800 + io];
        #pragma unroll
        for (int q = 0; q < 4; q++){
            acc[q].x += Ys[q*192 + g].x * kv;
            acc[q].y += Ys[q*192 + g].y * kv;
        }
    }
    float sc = rsqrtf(3840.0f);
    #pragma unroll
    for (int q = 0; q < 4; q++){
        int kk = blockIdx.x*4 + q;
        if (kk < K2N) g_Yk2[kk*800 + io] = make_float2(acc[q].x*sc, acc[q].y*sc);
    }
}

__global__ void kX2(){
    int k = blockIdx.x;
    int bi = blockIdx.y*128 + threadIdx.x;
    int l, m, n; decode6(k, l, m, n);
    int p = (m + 5)*11 + (n + 5);
    float2 acc = make_float2(0.f, 0.f);
    for (int j = 0; j < 20; j++){
        float d = g_DM2[k*20 + j];
        float2 v = g_bins[(p*20 + j)*BI2 + bi];
        acc.x += d * v.x; acc.y += d * v.y;
    }
    g_X2[k*BI2 + bi] = acc;
}

template<int L>
__global__ void kZ2(){
    const int l = (L - 1) / 2;
    const int base = c_SQ[l];
    int b = blockIdx.x, tid = threadIdx.x;
    __shared__ float2 A[L*L*20];
    for (int idx = tid; idx < L*L*20; idx += 256){
        int m = idx / (L*20), r = idx % (L*20), kk = r / 20, i = r % 20;
        A[idx] = g_X2[(base + m*L + kk)*BI2 + b*20 + i];
    }
    __syncthreads();
    for (int p = tid; p < L*40; p += 256){
        int n = p / 40, o = p % 40;
        float2 acc[L];
        #pragma unroll
        for (int m = 0; m < L; m++) acc[m] = make_float2(0.f, 0.f);
        for (int kk = 0; kk < L; kk++){
            const float2* Yrow = &g_Yk2[(base + n*L + kk)*800 + o];
            #pragma unroll 4
            for (int i = 0; i < 20; i++){
                float2 y = Yrow[i*40];
                #pragma unroll
                for (int m = 0; m < L; m++){
                    float2 a = A[m*L*20 + kk*20 + i];
                    acc[m].x += a.x*y.x - a.y*y.y;
                    acc[m].y += a.x*y.y + a.y*y.x;
                }
            }
        }
        #pragma unroll
        for (int m = 0; m < L; m++)
            g_Z2[(base + m*L + n)*5120 + b*40 + o] = acc[m];
    }
}

// Fused layer-2 synthesis + relu + quadrature + feature, Hermitian-halved.
__global__ void kSynth2(){
    __shared__ float2 ZL[286], E2[132], G2s[121], H2[72];
    __shared__ float  red[128];
    int o = blockIdx.x, b = blockIdx.y, tid = threadIdx.x;
    for (int t = tid; t < 286; t += 128) ZL[t] = g_Z2[t*5120 + b*40 + o];
    for (int p = tid; p < 132; p += 128) E2[p] = g_E2[p];
    __syncthreads();
    float facc = 0.f;
    for (int j = 0; j < 12; j++){
        for (int p = tid; p < 61; p += 128){
            int m = p/11 - 5, n = p%11 - 5;
            int lmin = max(abs(m), abs(n));
            float2 acc = make_float2(0.f, 0.f);
            const float* dt = &g_d2tab[(j*121 + p)*6];
            for (int l = lmin; l < 6; l++){
                int Ls = 2*l + 1;
                float2 z = ZL[c_SQ[l] + (m + l)*Ls + (n + l)];
                float d = dt[l];
                acc.x += d * z.x; acc.y += d * z.y;
            }
            G2s[p] = acc;
            G2s[120 - p] = make_float2(acc.x, -acc.y);
        }
        __syncthreads();
        for (int p = tid; p < 72; p += 128){
            int mi = p / 12, a3 = p % 12;   // mi 0..5 -> m=-5..0
            float2 acc = make_float2(0.f, 0.f);
            #pragma unroll
            for (int ni = 0; ni < 11; ni++){
                float2 g = G2s[mi*11 + ni], e = E2[ni*12 + a3];
                acc.x += g.x*e.x - g.y*e.y;
                acc.y += g.x*e.y + g.y*e.x;
            }
            H2[p] = acc;
        }
        __syncthreads();
        float wj = g_w2j[j];
        for (int p = tid; p < 144; p += 128){
            int a2 = p / 12, a3 = p % 12;
            float v = H2[5*12 + a3].x;
            #pragma unroll
            for (int mi = 0; mi < 5; mi++){
                float2 h = H2[mi*12 + a3], e = E2[mi*12 + a2];
                v += 2.f * (h.x*e.x - h.y*e.y);
            }
            facc += wj * fmaxf(v, 0.f);
        }
        __syncthreads();
    }
    red[tid] = facc;
    __syncthreads();
    for (int s = 64; s > 0; s >>= 1){
        if (tid < s) red[tid] += red[tid + s];
        __syncthreads();
    }
    if (tid == 0){
        const float INTEG = (float)((TWOPI_D/12.0)*(TWOPI_D/12.0));
        g_feat[b*40 + o] = INTEG * red[0];
    }
}

__global__ void kOut(const float* __restrict__ wout, const float* __restrict__ bias,
                     float* __restrict__ out){
    int g = blockIdx.x*128 + threadIdx.x;
    if (g >= 1280) return;
    int b = g / 10, fo = g % 10;
    float s = bias[fo];
    #pragma unroll
    for (int o = 0; o < 40; o++) s += g_feat[b*40 + o] * wout[fo*40 + o];
    out[g] = s;
}

// ---------------------------------------------------------------------------
extern "C" void kernel_launch(void* const* d_in, const int* in_sizes, int n_in,
                              void* d_out, int out_size){
    (void)in_sizes; (void)n_in; (void)out_size;
    const float* x  = (const float*)d_in[0];
    const float* k1 = (const float*)d_in[1];
    const float* k2 = (const float*)d_in[2];
    const float* wo = (const float*)d_in[3];
    const float* bo = (const float*)d_in[4];
    float* out = (float*)d_out;

    kWeights<<<1, 128>>>();
    kRawAll <<<146, 256>>>();
    kAsmAll <<<588, 256>>>();

    kDFT1  <<<dim3(60, 19), 128>>>(x);
    kX1    <<<100, 128>>>();
    kYk1   <<<20, 128>>>(k1);
    kSynth1<<<dim3(20, 128), 256>>>();

    kK2T   <<<1200, 128>>>(k2);
    kYk2   <<<dim3(72, 7), 128>>>();
    kX2    <<<dim3(286, 20), 128>>>();

    kZ2<1> <<<128, 256>>>();
    kZ2<3> <<<128, 256>>>();
    kZ2<5> <<<128, 256>>>();
    kZ2<7> <<<128, 256>>>();
    kZ2<9> <<<128, 256>>>();
    kZ2<11><<<128, 256>>>();

    kSynth2<<<dim3(40, 128), 128>>>();
    kOut   <<<10, 128>>>(wo, bo, out);
}

// round 13
// speedup vs baseline: 1.8856x; 1.2122x over previous
#include <cuda_runtime.h>
#include <math.h>

#define PI_D    3.141592653589793238462643383279
#define TWOPI_D 6.283185307179586476925286766559

// ---- problem sizes ----
#define NBATCH 128
#define K1N    100     // sum (2l+1), l<10
#define K2N    286     // sum (2l+1)^2, l<6
#define BI2    2560    // NBATCH * F1(20)

__constant__ int c_SQ[7]    = {0,1,10,35,84,165,286};                 // prefix (2l+1)^2, l<6
__constant__ int c_SQ10[11] = {0,1,10,35,84,165,286,455,680,969,1330};// prefix l<10

__constant__ double c_fact[19] = {
    1.0,1.0,2.0,6.0,24.0,120.0,720.0,5040.0,40320.0,362880.0,
    3628800.0,39916800.0,479001600.0,6227020800.0,87178291200.0,
    1307674368000.0,20922789888000.0,355687428096000.0,6402373705728000.0};
__constant__ double c_rfact[19] = {
    1.0,1.0,1.0/2.0,1.0/6.0,1.0/24.0,1.0/120.0,1.0/720.0,1.0/5040.0,
    1.0/40320.0,1.0/362880.0,1.0/3628800.0,1.0/39916800.0,1.0/479001600.0,
    1.0/6227020800.0,1.0/87178291200.0,1.0/1307674368000.0,
    1.0/20922789888000.0,1.0/355687428096000.0,1.0/6402373705728000.0};

// ---- raw wigner tables (dedup) ----
__device__ float g_dB1[20*1330];
__device__ float g_dS2[3*286];
__device__ float g_dS2m0[3*100];
__device__ float g_dB2[12*286];
__device__ float g_dBm0[60*100];
__device__ float g_win[60], g_w1[20], g_w2j[12];

// ---- assembled tables ----
__device__ float  g_DM1[K1N*60];
__device__ float2 g_cY1[K1N*24];
__device__ float  g_d1tab[20*361*10];
__device__ float  g_DM2[K2N*20];
__device__ float2 g_cY2B[K2N*192];
__device__ float  g_d2tab[12*121*6];
__device__ float2 g_E1[380];
__device__ float2 g_E2[132];

// ---- intermediates ----
__device__ float2 g_xb[19*60*NBATCH];
__device__ float2 g_X1[K1N*NBATCH];
__device__ float2 g_Yk1[20*K1N];
__device__ float2 g_X2[K2N*BI2];
__device__ float  g_K2T[192*800];
__device__ float2 g_Yk2[K2N*800];
__device__ float2 g_Z2[K2N*NBATCH*40];
__device__ float  g_feat[NBATCH*40];

// ---------------------------------------------------------------------------
__device__ double wig_fast(int l, int mp, int m, double beta){
    double cb = cos(0.5*beta), sb = sin(0.5*beta);
    int s0 = (m - mp > 0) ? (m - mp) : 0;
    int s1 = (l + m < l - mp) ? (l + m) : (l - mp);
    if (s1 < s0) return 0.0;
    double pref = sqrt(c_fact[l+mp]*c_fact[l-mp]*c_fact[l+m]*c_fact[l-m]);
    int ec = 2*l + m - mp - 2*s0, es = mp - m + 2*s0;
    double pw = 1.0;
    for (int i = 0; i < ec; i++) pw *= cb;
    for (int i = 0; i < es; i++) pw *= sb;
    double ratio = (sb*sb)/(cb*cb);
    double sum = 0.0;
    for (int s = s0; s <= s1; s++){
        double t = c_rfact[l+m-s]*c_rfact[s]*c_rfact[mp-m+s]*c_rfact[l-mp-s]*pw;
        sum += ((mp - m + s) & 1) ? -t : t;
        pw *= ratio;
    }
    return pref * sum;
}
__device__ __forceinline__ void decode6(int k, int &l, int &m, int &n){
    l = 0; while (k >= c_SQ[l+1]) l++;
    int r = k - c_SQ[l], L = 2*l+1; m = r/L - l; n = r%L - l;
}
__device__ __forceinline__ void decode10(int k, int &l, int &m, int &n){
    l = 0; while (k >= c_SQ10[l+1]) l++;
    int r = k - c_SQ10[l], L = 2*l+1; m = r/L - l; n = r%L - l;
}

// ---------------------------------------------------------------------------
__global__ void kWeights(){
    int t = threadIdx.x;
    if (t < 60){
        double beta = PI_D*(2*t+1)/120.0, s = 0.0;
        for (int k = 0; k < 30; k++) s += sin(beta*(2*k+1))/(2*k+1);
        g_win[t] = (float)((2.0/30.0)*sin(beta)*s);
    } else if (t < 80){
        int j = t - 60;
        double beta = PI_D*(2*j+1)/40.0, s = 0.0;
        for (int k = 0; k < 10; k++) s += sin(beta*(2*k+1))/(2*k+1);
        g_w1[j] = (float)((2.0/10.0)*sin(beta)*s);
    } else if (t < 92){
        int j = t - 80;
        double beta = PI_D*(2*j+1)/24.0, s = 0.0;
        for (int k = 0; k < 6; k++) s += sin(beta*(2*k+1))/(2*k+1);
        g_w2j[j] = (float)((2.0/6.0)*sin(beta)*s);
    }
}

__global__ void kRawAll(){
    int id = blockIdx.x*256 + threadIdx.x;
    if (id < 26600){
        int j = id/1330, k = id%1330, l, m, n; decode10(k, l, m, n);
        g_dB1[id] = (float)wig_fast(l, m, n, PI_D*(2*j+1)/40.0);
    } else if (id < 27458){
        int r = id - 26600, bi = r/286, k = r%286, l, m, n; decode6(k, l, m, n);
        g_dS2[r] = (float)wig_fast(l, m, n, (bi+1)*PI_D/24.0);
    } else if (id < 27758){
        int r = id - 27458, bi = r/100, k = r%100;
        int l = (int)(sqrt((double)k)+1e-9), m = k - l*l - l;
        g_dS2m0[r] = (float)wig_fast(l, m, 0, (bi+1)*PI_D/24.0);
    } else if (id < 31190){
        int r = id - 27758, j = r/286, k = r%286, l, m, n; decode6(k, l, m, n);
        g_dB2[r] = (float)wig_fast(l, m, n, PI_D*(2*j+1)/24.0);
    } else if (id < 37190){
        int r = id - 31190, j = r/100, k = r%100;
        int l = (int)(sqrt((double)k)+1e-9), m = k - l*l - l;
        g_dBm0[r] = (float)wig_fast(l, m, 0, PI_D*(2*j+1)/120.0);
    }
}

__global__ void kAsmAll(){
    int id = blockIdx.x*256 + threadIdx.x;
    if (id < 6000){
        int k = id/60, j = id%60;
        g_DM1[id] = g_dBm0[j*100 + k] * g_win[j];
    } else if (id < 8400){
        int r = id - 6000, k = r/24, g = r%24;
        int l = (int)(sqrt((double)k)+1e-9), m = k - l*l - l;
        int bi = g/8, ai = g%8;
        double d = (double)g_dS2m0[bi*100 + k];
        double ph = (double)m * (TWOPI_D*ai/8.0);
        double s, c; sincos(ph, &s, &c);
        g_cY1[r] = make_float2((float)(d*c), (float)(d*s));
    } else if (id < 80600){
        int r = id - 8400;
        int l = r%10, q = r/10, p = q%361, j = q/361;
        int m = p/19 - 9, n = p%19 - 9;
        float v = 0.f;
        if (l >= max(abs(m), abs(n)))
            v = (float)(2*l+1) * g_dB1[j*1330 + c_SQ10[l] + (m+l)*(2*l+1) + (n+l)];
        g_d1tab[r] = v;
    } else if (id < 86320){
        int r = id - 80600, k = r/20, j = r%20;
        g_DM2[r] = g_w1[j] * g_dB1[j*1330 + k];
    } else if (id < 141232){
        int r = id - 86320, k = r/192, g = r%192;
        int l, m, n; decode6(k, l, m, n);
        int bi = g/64, ai = (g/8)%8, ci = g%8;
        double alpha = TWOPI_D*ai/8.0;
        double gamma = (-TWOPI_D + (PI_D/2.0)*ci) - alpha;
        double d = (double)g_dS2[bi*286 + k];
        double ph = m*alpha + n*gamma;
        double s, c; sincos(ph, &s, &c);
        g_cY2B[r] = make_float2((float)(d*c), (float)(d*s));
    } else if (id < 149944){
        int r = id - 141232;
        int l = r%6, q = r/6, p = q%121, j = q/121;
        int m = p/11 - 5, n = p%11 - 5;
        float v = 0.f;
        if (l >= max(abs(m), abs(n)))
            v = (float)(2*l+1) * g_dB2[j*286 + c_SQ[l] + (m+l)*(2*l+1) + (n+l)];
        g_d2tab[r] = v;
    } else if (id < 150324){
        int r = id - 149944, mi = r/20, a = r%20;
        double ang = (double)(mi-9) * (TWOPI_D/20.0) * a;
        double s, c; sincos(ang, &s, &c);
        g_E1[r] = make_float2((float)c, (float)s);
    } else if (id < 150456){
        int r = id - 150324, mi = r/12, a = r%12;
        double ang = (double)(mi-5) * (TWOPI_D/12.0) * a;
        double s, c; sincos(ang, &s, &c);
        g_E2[r] = make_float2((float)c, (float)s);
    }
}

// ---------------------------------------------------------------------------
// Stage kernels
// ---------------------------------------------------------------------------
// One block per j: stage x[:,j,:] + twiddles in smem, compute all (b, mi).
__global__ void kDFT1(const float* __restrict__ x){
    __shared__ float  xs[128*60];
    __shared__ float2 tw[19*61];    // padded row (61) to avoid bank conflicts
    int j = blockIdx.x, tid = threadIdx.x;
    for (int idx = tid; idx < 7680; idx += 256){
        int b = idx / 60, a = idx % 60;
        xs[idx] = x[b*3600 + j*60 + a];
    }
    for (int idx = tid; idx < 1140; idx += 256){
        int mi = idx / 60, a = idx % 60;
        float ang = -(float)(mi - 9) * (6.28318530717958647f/60.f) * (float)a;
        float s, c; sincosf(ang, &s, &c);
        tw[mi*61 + a] = make_float2(c, s);
    }
    __syncthreads();
    for (int p = tid; p < 2432; p += 256){
        int b = p / 19, mi = p % 19;
        const float*  xr = &xs[b*60];
        const float2* tr = &tw[mi*61];
        float2 acc = make_float2(0.f, 0.f);
        #pragma unroll 4
        for (int a = 0; a < 60; a++){
            float v = xr[a];
            acc.x += v * tr[a].x;
            acc.y += v * tr[a].y;
        }
        acc.x *= (1.f/60.f); acc.y *= (1.f/60.f);
        g_xb[(mi*60 + j)*NBATCH + b] = acc;
    }
}

__global__ void kX1(){
    int k = blockIdx.x, b = threadIdx.x;
    int l = (int)(sqrt((double)k) + 1e-9);
    int mi = (k - l*l - l) + 9;
    float2 acc = make_float2(0.f, 0.f);
    for (int j = 0; j < 60; j++){
        float d = g_DM1[k*60 + j];
        float2 v = g_xb[(mi*60 + j)*NBATCH + b];
        acc.x += d * v.x; acc.y += d * v.y;
    }
    g_X1[k*NBATCH + b] = acc;
}

__global__ void kYk1(const float* __restrict__ k1){
    int o = blockIdx.x, k = threadIdx.x;
    if (k >= K1N) return;
    float2 acc = make_float2(0.f, 0.f);
    for (int g = 0; g < 24; g++){
        float w = k1[o*24 + g];
        float2 y = g_cY1[k*24 + g];
        acc.x += w * y.x; acc.y += w * y.y;
    }
    float sc = rsqrtf(24.0f);
    g_Yk1[o*K1N + k] = make_float2(acc.x*sc, acc.y*sc);
}

// Fused layer-1 synthesis + relu + layer-2 fft2 bins + X2 reduction over j.
// Hermitian-halved everywhere. One block per (o,b); X2 kept in registers.
__global__ void kSynth1(){
    __shared__ float2 XL[100], YL[100], E[380], prod[1810], G[361], H[200], T2[220], BINS[121];
    __shared__ float  GR[400];
    int o = blockIdx.x, b = blockIdx.y, tid = threadIdx.x;

    // per-thread X2 accumulators: k = tid, and k = tid+256 (tid<30)
    int lA, mA, nA; decode6(tid, lA, mA, nA);
    int pA = (mA + 5)*11 + (nA + 5);
    int kB = tid + 256;
    int pB = 0;
    if (kB < K2N){ int lB, mB, nB; decode6(kB, lB, mB, nB); pB = (mB + 5)*11 + (nB + 5); }
    float2 accA = make_float2(0.f, 0.f), accB = make_float2(0.f, 0.f);

    for (int p = tid; p < 100; p += 256){
        XL[p] = g_X1[p*NBATCH + b];
        YL[p] = g_Yk1[o*K1N + p];
    }
    for (int p = tid; p < 380; p += 256) E[p] = g_E1[p];
    __syncthreads();
    for (int p = tid; p < 181; p += 256){
        int m = p/19 - 9, n = p%19 - 9;
        int lmin = max(abs(m), abs(n));
        for (int l = lmin; l < 10; l++){
            float2 xa = XL[l*l + m + l], ya = YL[l*l + n + l];
            prod[p*10 + l] = make_float2(xa.x*ya.x - xa.y*ya.y, xa.x*ya.y + xa.y*ya.x);
        }
    }
    __syncthreads();

    for (int j = 0; j < 20; j++){
        for (int p = tid; p < 181; p += 256){
            int m = p/19 - 9, n = p%19 - 9;
            int lmin = max(abs(m), abs(n));
            float2 acc = make_float2(0.f, 0.f);
            const float* dt = &g_d1tab[(j*361 + p)*10];
            for (int l = lmin; l < 10; l++){
                float d = dt[l];
                float2 pr = prod[p*10 + l];
                acc.x += d * pr.x; acc.y += d * pr.y;
            }
            G[p] = acc;
            G[360 - p] = make_float2(acc.x, -acc.y);
        }
        __syncthreads();
        for (int p = tid; p < 200; p += 256){
            int mi = p / 20, a3 = p % 20;
            float2 acc = make_float2(0.f, 0.f);
            #pragma unroll
            for (int ni = 0; ni < 19; ni++){
                float2 g = G[mi*19 + ni], e = E[ni*20 + a3];
                acc.x += g.x*e.x - g.y*e.y;
                acc.y += g.x*e.y + g.y*e.x;
            }
            H[p] = acc;
        }
        __syncthreads();
        for (int p = tid; p < 400; p += 256){
            int a2 = p / 20, a3 = p % 20;
            float v = H[9*20 + a3].x;
            #pragma unroll
            for (int mi = 0; mi < 9; mi++){
                float2 h = H[mi*20 + a3], e = E[mi*20 + a2];
                v += 2.f * (h.x*e.x - h.y*e.y);
            }
            GR[p] = fmaxf(v, 0.f);
        }
        __syncthreads();
        for (int p = tid; p < 120; p += 256){
            int ni2 = 5 + p/20, a2 = p%20;
            float2 acc = make_float2(0.f, 0.f);
            int row = (14 - ni2) * 20;
            for (int a3 = 0; a3 < 20; a3++){
                float g = GR[a2*20 + a3];
                float2 e = E[row + a3];
                acc.x += g * e.x; acc.y += g * e.y;
            }
            T2[ni2*20 + a2] = acc;
            if (ni2 > 5) T2[(10 - ni2)*20 + a2] = make_float2(acc.x, -acc.y);
        }
        __syncthreads();
        for (int p = tid; p < 61; p += 256){
            int mi2 = p / 11, ni2 = p % 11;
            float2 acc = make_float2(0.f, 0.f);
            int row = (14 - mi2) * 20;
            for (int a2 = 0; a2 < 20; a2++){
                float2 t = T2[ni2*20 + a2], e = E[row + a2];
                acc.x += t.x*e.x - t.y*e.y;
                acc.y += t.x*e.y + t.y*e.x;
            }
            acc.x *= (1.f/400.f); acc.y *= (1.f/400.f);
            BINS[p] = acc;
            if (p < 60) BINS[120 - p] = make_float2(acc.x, -acc.y);
        }
        __syncthreads();
        // X2 accumulation (registers; no trailing sync needed — next write to
        // BINS is 5 syncs away)
        {
            float dA = g_DM2[tid*20 + j];
            float2 vA = BINS[pA];
            accA.x += dA * vA.x; accA.y += dA * vA.y;
            if (kB < K2N){
                float dB = g_DM2[kB*20 + j];
                float2 vB = BINS[pB];
                accB.x += dB * vB.x; accB.y += dB * vB.y;
            }
        }
    }
    g_X2[tid*BI2 + b*20 + o] = accA;
    if (kB < K2N) g_X2[kB*BI2 + b*20 + o] = accB;
}

__global__ void kK2T(const float* __restrict__ k2){
    int id = blockIdx.x*128 + threadIdx.x;
    if (id < 153600){
        int io = id / 192, g = id % 192;
        g_K2T[g*800 + io] = k2[id];
    }
}

__global__ void kYk2(){
    __shared__ float2 Ys[4*192];
    int tid = threadIdx.x;
    int io = blockIdx.y*128 + tid;
    for (int idx = tid; idx < 768; idx += 128){
        int q = idx / 192, g = idx % 192;
        int kk = blockIdx.x*4 + q;
        Ys[idx] = (kk < K2N) ? g_cY2B[kk*192 + g] : make_float2(0.f, 0.f);
    }
    __syncthreads();
    if (io >= 800) return;
    float2 acc[4] = {{0,0},{0,0},{0,0},{0,0}};
    for (int g = 0; g < 192; g++){
        float kv = g_K2T[g*800 + io];
        #pragma unroll
        for (int q = 0; q < 4; q++){
            acc[q].x += Ys[q*192 + g].x * kv;
            acc[q].y += Ys[q*192 + g].y * kv;
        }
    }
    float sc = rsqrtf(3840.0f);
    #pragma unroll
    for (int q = 0; q < 4; q++){
        int kk = blockIdx.x*4 + q;
        if (kk < K2N) g_Yk2[kk*800 + io] = make_float2(acc[q].x*sc, acc[q].y*sc);
    }
}

// Z2 with Hermitian halving: compute n>=0 columns, mirror
// Z[-m,-n] = (-1)^{m+n} conj(Z[m,n]).
template<int L>
__global__ void kZ2(){
    const int l = (L - 1) / 2;
    const int base = c_SQ[l];
    const int NH = l + 1;
    int b = blockIdx.x, tid = threadIdx.x;
    __shared__ float2 A[L*L*20];
    for (int idx = tid; idx < L*L*20; idx += 256){
        int m = idx / (L*20), r = idx % (L*20), kk = r / 20, i = r % 20;
        A[idx] = g_X2[(base + m*L + kk)*BI2 + b*20 + i];
    }
    __syncthreads();
    for (int p = tid; p < NH*40; p += 256){
        int q = p / 40, o = p % 40;
        int n0 = l + q;
        float2 acc[L];
        #pragma unroll
        for (int m = 0; m < L; m++) acc[m] = make_float2(0.f, 0.f);
        for (int kk = 0; kk < L; kk++){
            const float2* Yrow = &g_Yk2[(base + n0*L + kk)*800 + o];
            #pragma unroll 4
            for (int i = 0; i < 20; i++){
                float2 y = Yrow[i*40];
                #pragma unroll
                for (int m = 0; m < L; m++){
                    float2 a = A[m*L*20 + kk*20 + i];
                    acc[m].x += a.x*y.x - a.y*y.y;
                    acc[m].y += a.x*y.y + a.y*y.x;
                }
            }
        }
        #pragma unroll
        for (int m = 0; m < L; m++){
            g_Z2[(base + m*L + n0)*5120 + b*40 + o] = acc[m];
            if (q > 0){
                float sgn = ((m + n0) & 1) ? -1.f : 1.f;
                g_Z2[(base + (2*l - m)*L + (2*l - n0))*5120 + b*40 + o] =
                    make_float2(sgn*acc[m].x, -sgn*acc[m].y);
            }
        }
    }
}

// Fused layer-2 synthesis + relu + quadrature + feature; 2 j per iteration.
__global__ void kSynth2(){
    __shared__ float2 ZL[286], E2[132], G2s[2][121], H2[2][72];
    __shared__ float  red[128];
    int o = blockIdx.x, b = blockIdx.y, tid = threadIdx.x;
    for (int t = tid; t < 286; t += 128) ZL[t] = g_Z2[t*5120 + b*40 + o];
    for (int p = tid; p < 132; p += 128) E2[p] = g_E2[p];
    __syncthreads();
    float facc = 0.f;
    for (int jj = 0; jj < 6; jj++){
        int j0 = 2*jj;
        for (int p = tid; p < 122; p += 128){
            int j2 = p / 61, pp = p % 61;
            int m = pp/11 - 5, n = pp%11 - 5;
            int lmin = max(abs(m), abs(n));
            float2 acc = make_float2(0.f, 0.f);
            const float* dt = &g_d2tab[((j0 + j2)*121 + pp)*6];
            for (int l = lmin; l < 6; l++){
                int Ls = 2*l + 1;
                float2 z = ZL[c_SQ[l] + (m + l)*Ls + (n + l)];
                float d = dt[l];
                acc.x += d * z.x; acc.y += d * z.y;
            }
            G2s[j2][pp] = acc;
            G2s[j2][120 - pp] = make_float2(acc.x, -acc.y);
        }
        __syncthreads();
        for (int p = tid; p < 144; p += 128){
            int j2 = p / 72, q = p % 72;
            int mi = q / 12, a3 = q % 12;
            float2 acc = make_float2(0.f, 0.f);
            #pragma unroll
            for (int ni = 0; ni < 11; ni++){
                float2 g = G2s[j2][mi*11 + ni], e = E2[ni*12 + a3];
                acc.x += g.x*e.x - g.y*e.y;
                acc.y += g.x*e.y + g.y*e.x;
            }
            H2[j2][q] = acc;
        }
        __syncthreads();
        for (int p = tid; p < 288; p += 128){
            int j2 = p / 144, q = p % 144;
            int a2 = q / 12, a3 = q % 12;
            float v = H2[j2][5*12 + a3].x;
            #pragma unroll
            for (int mi = 0; mi < 5; mi++){
                float2 h = H2[j2][mi*12 + a3], e = E2[mi*12 + a2];
                v += 2.f * (h.x*e.x - h.y*e.y);
            }
            facc += g_w2j[j0 + j2] * fmaxf(v, 0.f);
        }
        __syncthreads();
    }
    red[tid] = facc;
    __syncthreads();
    for (int s = 64; s > 0; s >>= 1){
        if (tid < s) red[tid] += red[tid + s];
        __syncthreads();
    }
    if (tid == 0){
        const float INTEG = (float)((TWOPI_D/12.0)*(TWOPI_D/12.0));
        g_feat[b*40 + o] = INTEG * red[0];
    }
}

__global__ void kOut(const float* __restrict__ wout, const float* __restrict__ bias,
                     float* __restrict__ out){
    int g = blockIdx.x*128 + threadIdx.x;
    if (g >= 1280) return;
    int b = g / 10, fo = g % 10;
    float s = bias[fo];
    #pragma unroll
    for (int o = 0; o < 40; o++) s += g_feat[b*40 + o] * wout[fo*40 + o];
    out[g] = s;
}

// ---------------------------------------------------------------------------
extern "C" void kernel_launch(void* const* d_in, const int* in_sizes, int n_in,
                              void* d_out, int out_size){
    (void)in_sizes; (void)n_in; (void)out_size;
    const float* x  = (const float*)d_in[0];
    const float* k1 = (const float*)d_in[1];
    const float* k2 = (const float*)d_in[2];
    const float* wo = (const float*)d_in[3];
    const float* bo = (const float*)d_in[4];
    float* out = (float*)d_out;

    kWeights<<<1, 128>>>();
    kRawAll <<<146, 256>>>();
    kAsmAll <<<588, 256>>>();

    kDFT1  <<<60, 256>>>(x);
    kX1    <<<100, 128>>>();
    kYk1   <<<20, 128>>>(k1);
    kK2T   <<<1200, 128>>>(k2);
    kYk2   <<<dim3(72, 7), 128>>>();
    kSynth1<<<dim3(20, 128), 256>>>();

    kZ2<1> <<<128, 256>>>();
    kZ2<3> <<<128, 256>>>();
    kZ2<5> <<<128, 256>>>();
    kZ2<7> <<<128, 256>>>();
    kZ2<9> <<<128, 256>>>();
    kZ2<11><<<128, 256>>>();

    kSynth2<<<dim3(40, 128), 128>>>();
    kOut   <<<10, 128>>>(wo, bo, out);
}

// round 17
// speedup vs baseline: 1.9019x; 1.0087x over previous
#include <cuda_runtime.h>
#include <math.h>

#define PI_D    3.141592653589793238462643383279
#define TWOPI_D 6.283185307179586476925286766559

// ---- problem sizes ----
#define NBATCH 128
#define K1N    100     // sum (2l+1), l<10
#define K2N    286     // sum (2l+1)^2, l<6
#define BI2    2560    // NBATCH * F1(20)

__constant__ int c_SQ[7]    = {0,1,10,35,84,165,286};
__constant__ int c_SQ10[11] = {0,1,10,35,84,165,286,455,680,969,1330};

__constant__ double c_fact[19] = {
    1.0,1.0,2.0,6.0,24.0,120.0,720.0,5040.0,40320.0,362880.0,
    3628800.0,39916800.0,479001600.0,6227020800.0,87178291200.0,
    1307674368000.0,20922789888000.0,355687428096000.0,6402373705728000.0};
__constant__ double c_rfact[19] = {
    1.0,1.0,1.0/2.0,1.0/6.0,1.0/24.0,1.0/120.0,1.0/720.0,1.0/5040.0,
    1.0/40320.0,1.0/362880.0,1.0/3628800.0,1.0/39916800.0,1.0/479001600.0,
    1.0/6227020800.0,1.0/87178291200.0,1.0/1307674368000.0,
    1.0/20922789888000.0,1.0/355687428096000.0,1.0/6402373705728000.0};

// ---- raw wigner tables ----
__device__ float g_dB1[20*1330];
__device__ float g_dS2[3*286];
__device__ float g_dS2m0[3*100];
__device__ float g_dB2[12*286];
__device__ float g_dBm0[60*100];
__device__ float g_win[60], g_w1[20], g_w2j[12];

// ---- assembled tables ----
__device__ float  g_DM1[K1N*60];
__device__ float2 g_cY1[K1N*24];
__device__ float  g_d1tab[20*361*10];
__device__ float  g_DM2[K2N*20];
__device__ float2 g_cY2B[K2N*192];
__device__ float  g_d2tab[12*121*6];
__device__ float2 g_E1[380];
__device__ float2 g_E2[132];

// ---- intermediates ----
__device__ float2 g_xb[10*60*NBATCH];     // only m>=0 bins
__device__ float2 g_X1[K1N*NBATCH];
__device__ float2 g_Yk1[20*K1N];
__device__ float2 g_X2[K2N*BI2];
__device__ float  g_K2T[192*800];
__device__ float2 g_Yk2[K2N*800];
__device__ float2 g_Z2[K2N*NBATCH*40];
__device__ float  g_feat[NBATCH*40];

// ---------------------------------------------------------------------------
__device__ double wig_fast(int l, int mp, int m, double beta){
    double cb = cos(0.5*beta), sb = sin(0.5*beta);
    int s0 = (m - mp > 0) ? (m - mp) : 0;
    int s1 = (l + m < l - mp) ? (l + m) : (l - mp);
    if (s1 < s0) return 0.0;
    double pref = sqrt(c_fact[l+mp]*c_fact[l-mp]*c_fact[l+m]*c_fact[l-m]);
    int ec = 2*l + m - mp - 2*s0, es = mp - m + 2*s0;
    double pw = 1.0;
    for (int i = 0; i < ec; i++) pw *= cb;
    for (int i = 0; i < es; i++) pw *= sb;
    double ratio = (sb*sb)/(cb*cb);
    double sum = 0.0;
    for (int s = s0; s <= s1; s++){
        double t = c_rfact[l+m-s]*c_rfact[s]*c_rfact[mp-m+s]*c_rfact[l-mp-s]*pw;
        sum += ((mp - m + s) & 1) ? -t : t;
        pw *= ratio;
    }
    return pref * sum;
}
__device__ __forceinline__ void decode6(int k, int &l, int &m, int &n){
    l = 0; while (k >= c_SQ[l+1]) l++;
    int r = k - c_SQ[l], L = 2*l+1; m = r/L - l; n = r%L - l;
}
__device__ __forceinline__ void decode10(int k, int &l, int &m, int &n){
    l = 0; while (k >= c_SQ10[l+1]) l++;
    int r = k - c_SQ10[l], L = 2*l+1; m = r/L - l; n = r%L - l;
}

// ---------------------------------------------------------------------------
// Raw wigner evals + quadrature weights (deduped)
__global__ void kRawAll(){
    int id = blockIdx.x*256 + threadIdx.x;
    if (id < 26600){
        int j = id/1330, k = id%1330, l, m, n; decode10(k, l, m, n);
        g_dB1[id] = (float)wig_fast(l, m, n, PI_D*(2*j+1)/40.0);
    } else if (id < 27458){
        int r = id - 26600, bi = r/286, k = r%286, l, m, n; decode6(k, l, m, n);
        g_dS2[r] = (float)wig_fast(l, m, n, (bi+1)*PI_D/24.0);
    } else if (id < 27758){
        int r = id - 27458, bi = r/100, k = r%100;
        int l = (int)(sqrt((double)k)+1e-9), m = k - l*l - l;
        g_dS2m0[r] = (float)wig_fast(l, m, 0, (bi+1)*PI_D/24.0);
    } else if (id < 31190){
        int r = id - 27758, j = r/286, k = r%286, l, m, n; decode6(k, l, m, n);
        g_dB2[r] = (float)wig_fast(l, m, n, PI_D*(2*j+1)/24.0);
    } else if (id < 37190){
        int r = id - 31190, j = r/100, k = r%100;
        int l = (int)(sqrt((double)k)+1e-9), m = k - l*l - l;
        g_dBm0[r] = (float)wig_fast(l, m, 0, PI_D*(2*j+1)/120.0);
    } else if (id < 37250){
        int t = id - 37190;
        double beta = PI_D*(2*t+1)/120.0, s = 0.0;
        for (int k = 0; k < 30; k++) s += sin(beta*(2*k+1))/(2*k+1);
        g_win[t] = (float)((2.0/30.0)*sin(beta)*s);
    } else if (id < 37270){
        int j = id - 37250;
        double beta = PI_D*(2*j+1)/40.0, s = 0.0;
        for (int k = 0; k < 10; k++) s += sin(beta*(2*k+1))/(2*k+1);
        g_w1[j] = (float)((2.0/10.0)*sin(beta)*s);
    } else if (id < 37282){
        int j = id - 37270;
        double beta = PI_D*(2*j+1)/24.0, s = 0.0;
        for (int k = 0; k < 6; k++) s += sin(beta*(2*k+1))/(2*k+1);
        g_w2j[j] = (float)((2.0/6.0)*sin(beta)*s);
    }
}

__global__ void kAsmAll(){
    int id = blockIdx.x*256 + threadIdx.x;
    if (id < 6000){
        int k = id/60, j = id%60;
        g_DM1[id] = g_dBm0[j*100 + k] * g_win[j];
    } else if (id < 8400){
        int r = id - 6000, k = r/24, g = r%24;
        int l = (int)(sqrt((double)k)+1e-9), m = k - l*l - l;
        int bi = g/8, ai = g%8;
        double d = (double)g_dS2m0[bi*100 + k];
        double ph = (double)m * (TWOPI_D*ai/8.0);
        double s, c; sincos(ph, &s, &c);
        g_cY1[r] = make_float2((float)(d*c), (float)(d*s));
    } else if (id < 80600){
        int r = id - 8400;
        int l = r%10, q = r/10, p = q%361, j = q/361;
        int m = p/19 - 9, n = p%19 - 9;
        float v = 0.f;
        if (l >= max(abs(m), abs(n)))
            v = (float)(2*l+1) * g_dB1[j*1330 + c_SQ10[l] + (m+l)*(2*l+1) + (n+l)];
        g_d1tab[r] = v;
    } else if (id < 86320){
        int r = id - 80600, k = r/20, j = r%20;
        g_DM2[r] = g_w1[j] * g_dB1[j*1330 + k];
    } else if (id < 141232){
        int r = id - 86320, k = r/192, g = r%192;
        int l, m, n; decode6(k, l, m, n);
        int bi = g/64, ai = (g/8)%8, ci = g%8;
        double alpha = TWOPI_D*ai/8.0;
        double gamma = (-TWOPI_D + (PI_D/2.0)*ci) - alpha;
        double d = (double)g_dS2[bi*286 + k];
        double ph = m*alpha + n*gamma;
        double s, c; sincos(ph, &s, &c);
        g_cY2B[r] = make_float2((float)(d*c), (float)(d*s));
    } else if (id < 149944){
        int r = id - 141232;
        int l = r%6, q = r/6, p = q%121, j = q/121;
        int m = p/11 - 5, n = p%11 - 5;
        float v = 0.f;
        if (l >= max(abs(m), abs(n)))
            v = (float)(2*l+1) * g_dB2[j*286 + c_SQ[l] + (m+l)*(2*l+1) + (n+l)];
        g_d2tab[r] = v;
    } else if (id < 150324){
        int r = id - 149944, mi = r/20, a = r%20;
        double ang = (double)(mi-9) * (TWOPI_D/20.0) * a;
        double s, c; sincos(ang, &s, &c);
        g_E1[r] = make_float2((float)c, (float)s);
    } else if (id < 150456){
        int r = id - 150324, mi = r/12, a = r%12;
        double ang = (double)(mi-5) * (TWOPI_D/12.0) * a;
        double s, c; sincos(ang, &s, &c);
        g_E2[r] = make_float2((float)c, (float)s);
    }
}

// ---------------------------------------------------------------------------
// alpha-DFT of input, m>=0 bins only. Blocks: (j, batch-half).
__global__ void kDFT1(const float* __restrict__ x){
    __shared__ float  xs[64*60];
    __shared__ float2 tw[10*61];
    int j = blockIdx.x / 2, b0 = (blockIdx.x & 1) * 64;
    int tid = threadIdx.x;
    for (int idx = tid; idx < 3840; idx += 256){
        int b = idx / 60, a = idx % 60;
        xs[idx] = x[(b0 + b)*3600 + j*60 + a];
    }
    for (int idx = tid; idx < 600; idx += 256){
        int mi = idx / 60, a = idx % 60;
        float ang = -(float)mi * (6.28318530717958647f/60.f) * (float)a;
        float s, c; sincosf(ang, &s, &c);
        tw[mi*61 + a] = make_float2(c, s);
    }
    __syncthreads();
    for (int p = tid; p < 640; p += 256){
        int b = p / 10, mi = p % 10;
        const float*  xr = &xs[b*60];
        const float2* tr = &tw[mi*61];
        float2 acc = make_float2(0.f, 0.f);
        #pragma unroll 4
        for (int a = 0; a < 60; a++){
            float v = xr[a];
            acc.x += v * tr[a].x;
            acc.y += v * tr[a].y;
        }
        acc.x *= (1.f/60.f); acc.y *= (1.f/60.f);
        g_xb[(mi*60 + j)*NBATCH + b0 + b] = acc;
    }
}

// X1 for m>=0 directly; mirror X1[l,-m] = (-1)^m conj(X1[l,m]).
__global__ void kX1(){
    int k = blockIdx.x, b = threadIdx.x;
    int l = (int)(sqrt((double)k) + 1e-9);
    int m = k - l*l - l;
    if (m < 0) return;
    float2 acc = make_float2(0.f, 0.f);
    for (int j = 0; j < 60; j++){
        float d = g_DM1[k*60 + j];
        float2 v = g_xb[(m*60 + j)*NBATCH + b];
        acc.x += d * v.x; acc.y += d * v.y;
    }
    g_X1[k*NBATCH + b] = acc;
    if (m > 0){
        float s = (m & 1) ? -1.f : 1.f;
        g_X1[(k - 2*m)*NBATCH + b] = make_float2(s*acc.x, -s*acc.y);
    }
}

__global__ void kYk1(const float* __restrict__ k1){
    int o = blockIdx.x, k = threadIdx.x;
    if (k >= K1N) return;
    float2 acc = make_float2(0.f, 0.f);
    for (int g = 0; g < 24; g++){
        float w = k1[o*24 + g];
        float2 y = g_cY1[k*24 + g];
        acc.x += w * y.x; acc.y += w * y.y;
    }
    float sc = rsqrtf(24.0f);
    g_Yk1[o*K1N + k] = make_float2(acc.x*sc, acc.y*sc);
}

// ---------------------------------------------------------------------------
// Fused layer-1 synthesis + relu + layer-2 fft2 bins + X2 reduction.
// 5 j per chunk, register-tiled stages, Hermitian-halved, dynamic smem.
// ---------------------------------------------------------------------------
#define SMEM1_BYTES 61000

__global__ void kSynth1(){
    extern __shared__ float2 smbuf[];
    float2* XL   = smbuf;            // 100
    float2* YL   = XL + 100;         // 100
    float2* E    = YL + 100;         // 380
    float2* prod = E + 380;          // 1810
    float2* Gd   = prod + 1810;      // 5*361
    float2* Hs   = Gd + 1805;        // 5*200
    float2* T2s  = Hs + 1000;        // 5*220
    float2* BINS = T2s + 1100;       // 5*66
    float*  GR   = (float*)(BINS + 330); // 5*400

    int o = blockIdx.x, b = blockIdx.y, tid = threadIdx.x;

    // per-thread X2 accumulators: k = tid, k = tid+256
    int lA, mA, nA; decode6(tid, lA, mA, nA);
    int pA = (mA + 5)*11 + (nA + 5);
    int pAe = (pA <= 65) ? pA : (120 - pA);
    float sA = (pA <= 65) ? 1.f : -1.f;     // sign applied to imag
    int kB = tid + 256, pBe = 0; float sB = 1.f;
    if (kB < K2N){
        int lB, mB, nB; decode6(kB, lB, mB, nB);
        int pB = (mB + 5)*11 + (nB + 5);
        pBe = (pB <= 65) ? pB : (120 - pB);
        sB  = (pB <= 65) ? 1.f : -1.f;
    }
    float2 accA = make_float2(0.f, 0.f), accB = make_float2(0.f, 0.f);

    for (int p = tid; p < 100; p += 256){
        XL[p] = g_X1[p*NBATCH + b];
        YL[p] = g_Yk1[o*K1N + p];
    }
    for (int p = tid; p < 380; p += 256) E[p] = g_E1[p];
    __syncthreads();
    for (int p = tid; p < 181; p += 256){
        int m = p/19 - 9, n = p%19 - 9;
        int lmin = max(abs(m), abs(n));
        for (int l = lmin; l < 10; l++){
            float2 xa = XL[l*l + m + l], ya = YL[l*l + n + l];
            prod[p*10 + l] = make_float2(xa.x*ya.x - xa.y*ya.y, xa.x*ya.y + xa.y*ya.x);
        }
    }
    __syncthreads();

    for (int c = 0; c < 4; c++){
        // ---- Stage G: 905 items (jc, half-plane p) ----
        for (int it = tid; it < 905; it += 256){
            int jc = it / 181, p = it % 181;
            int j = c*5 + jc;
            int m = p/19 - 9, n = p%19 - 9;
            int lmin = max(abs(m), abs(n));
            float2 acc = make_float2(0.f, 0.f);
            const float* dt = &g_d1tab[(j*361 + p)*10];
            for (int l = lmin; l < 10; l++){
                float d = dt[l];
                float2 pr = prod[p*10 + l];
                acc.x += d * pr.x; acc.y += d * pr.y;
            }
            Gd[jc*361 + p] = acc;
            Gd[jc*361 + 360 - p] = make_float2(acc.x, -acc.y);
        }
        __syncthreads();
        // ---- Stage H: 250 items, 4 a3 per thread ----
        if (tid < 250){
            int jc = tid / 50, r = tid % 50, mi = r / 5, a3g = (r % 5)*4;
            float2 a0 = {0,0}, a1 = {0,0}, a2v = {0,0}, a3v = {0,0};
            const float2* Grow = &Gd[jc*361 + mi*19];
            #pragma unroll
            for (int ni = 0; ni < 19; ni++){
                float2 g = Grow[ni];
                const float2* er = &E[ni*20 + a3g];
                float2 e0 = er[0], e1 = er[1], e2 = er[2], e3 = er[3];
                a0.x += g.x*e0.x - g.y*e0.y; a0.y += g.x*e0.y + g.y*e0.x;
                a1.x += g.x*e1.x - g.y*e1.y; a1.y += g.x*e1.y + g.y*e1.x;
                a2v.x += g.x*e2.x - g.y*e2.y; a2v.y += g.x*e2.y + g.y*e2.x;
                a3v.x += g.x*e3.x - g.y*e3.y; a3v.y += g.x*e3.y + g.y*e3.x;
            }
            float2* hr = &Hs[jc*200 + mi*20 + a3g];
            hr[0] = a0; hr[1] = a1; hr[2] = a2v; hr[3] = a3v;
        }
        __syncthreads();
        // ---- Stage grid+relu: 500 items, 4 a3 per thread ----
        for (int it = tid; it < 500; it += 256){
            int jc = it / 100, r = it % 100, a2 = r / 5, a3g = (r % 5)*4;
            const float2* h0 = &Hs[jc*200 + 180 + a3g];
            float v0 = h0[0].x, v1 = h0[1].x, v2 = h0[2].x, v3 = h0[3].x;
            #pragma unroll
            for (int mi = 0; mi < 9; mi++){
                float2 e = E[mi*20 + a2];
                const float2* hr = &Hs[jc*200 + mi*20 + a3g];
                float2 h;
                h = hr[0]; v0 += 2.f*(h.x*e.x - h.y*e.y);
                h = hr[1]; v1 += 2.f*(h.x*e.x - h.y*e.y);
                h = hr[2]; v2 += 2.f*(h.x*e.x - h.y*e.y);
                h = hr[3]; v3 += 2.f*(h.x*e.x - h.y*e.y);
            }
            float* gr = &GR[jc*400 + a2*20 + a3g];
            gr[0] = fmaxf(v0, 0.f); gr[1] = fmaxf(v1, 0.f);
            gr[2] = fmaxf(v2, 0.f); gr[3] = fmaxf(v3, 0.f);
        }
        __syncthreads();
        // ---- Stage T2: 150 items, 2x2 tiles (2 n2 x 2 a2) ----
        if (tid < 150){
            int jc = tid / 30, r = tid % 30, n2p = r / 10, a2p = (r % 10)*2;
            int ni2a = 5 + 2*n2p;             // 5,7,9
            int rowa = (14 - ni2a)*20, rowb = rowa - 20;
            float2 c00 = {0,0}, c01 = {0,0}, c10 = {0,0}, c11 = {0,0};
            const float* g0r = &GR[jc*400 + a2p*20];
            const float* g1r = g0r + 20;
            #pragma unroll 4
            for (int a3 = 0; a3 < 20; a3++){
                float g0 = g0r[a3], g1 = g1r[a3];
                float2 ea = E[rowa + a3], eb = E[rowb + a3];
                c00.x += g0*ea.x; c00.y += g0*ea.y;
                c01.x += g1*ea.x; c01.y += g1*ea.y;
                c10.x += g0*eb.x; c10.y += g0*eb.y;
                c11.x += g1*eb.x; c11.y += g1*eb.y;
            }
            float2* t = &T2s[jc*220];
            t[ni2a*20 + a2p]     = c00;
            t[ni2a*20 + a2p + 1] = c01;
            t[(ni2a+1)*20 + a2p]     = c10;
            t[(ni2a+1)*20 + a2p + 1] = c11;
            if (ni2a > 5){
                t[(10-ni2a)*20 + a2p]     = make_float2(c00.x, -c00.y);
                t[(10-ni2a)*20 + a2p + 1] = make_float2(c01.x, -c01.y);
            }
            t[(9-ni2a)*20 + a2p]     = make_float2(c10.x, -c10.y);
            t[(9-ni2a)*20 + a2p + 1] = make_float2(c11.x, -c11.y);
        }
        __syncthreads();
        // ---- Stage bins: 180 items, rows mi2 0..5, 2 ni2 per thread ----
        if (tid < 180){
            int jc = tid / 36, r = tid % 36, mi2 = r / 6, np = r % 6;
            int ni2a = 2*np, ni2b = ni2a + 1;
            int row = (14 - mi2)*20;
            float2 ca = {0,0}, cb = {0,0};
            const float2* ta = &T2s[jc*220 + ni2a*20];
            const float2* tb = ta + 20;
            #pragma unroll 4
            for (int a2 = 0; a2 < 20; a2++){
                float2 e = E[row + a2];
                float2 t1 = ta[a2];
                ca.x += t1.x*e.x - t1.y*e.y;
                ca.y += t1.x*e.y + t1.y*e.x;
                if (ni2b < 11){
                    float2 t2 = tb[a2];
                    cb.x += t2.x*e.x - t2.y*e.y;
                    cb.y += t2.x*e.y + t2.y*e.x;
                }
            }
            BINS[jc*66 + mi2*11 + ni2a] = make_float2(ca.x*(1.f/400.f), ca.y*(1.f/400.f));
            if (ni2b < 11)
                BINS[jc*66 + mi2*11 + ni2b] = make_float2(cb.x*(1.f/400.f), cb.y*(1.f/400.f));
        }
        __syncthreads();
        // ---- X2 accumulation over the 5 j's of this chunk ----
        #pragma unroll
        for (int jc = 0; jc < 5; jc++){
            int j = c*5 + jc;
            float dA = g_DM2[tid*20 + j];
            float2 vA = BINS[jc*66 + pAe];
            accA.x += dA * vA.x; accA.y += dA * sA * vA.y;
            if (kB < K2N){
                float dB = g_DM2[kB*20 + j];
                float2 vB = BINS[jc*66 + pBe];
                accB.x += dB * vB.x; accB.y += dB * sB * vB.y;
            }
        }
    }
    g_X2[tid*BI2 + b*20 + o] = accA;
    if (kB < K2N) g_X2[kB*BI2 + b*20 + o] = accB;
}

// ---------------------------------------------------------------------------
__global__ void kK2T(const float* __restrict__ k2){
    int id = blockIdx.x*128 + threadIdx.x;
    if (id < 153600){
        int io = id / 192, g = id % 192;
        g_K2T[g*800 + io] = k2[id];
    }
}

__global__ void kYk2(){
    __shared__ float2 Ys[4*192];
    int tid = threadIdx.x;
    int io = blockIdx.y*128 + tid;
    for (int idx = tid; idx < 768; idx += 128){
        int q = idx / 192, g = idx % 192;
        int kk = blockIdx.x*4 + q;
        Ys[idx] = (kk < K2N) ? g_cY2B[kk*192 + g] : make_float2(0.f, 0.f);
    }
    __syncthreads();
    if (io >= 800) return;
    float2 acc[4] = {{0,0},{0,0},{0,0},{0,0}};
    for (int g = 0; g < 192; g++){
        float kv = g_K2T[g*800 + io];
        #pragma unroll
        for (int q = 0; q < 4; q++){
            acc[q].x += Ys[q*192 + g].x * kv;
            acc[q].y += Ys[q*192 + g].y * kv;
        }
    }
    float sc = rsqrtf(3840.0f);
    #pragma unroll
    for (int q = 0; q < 4; q++){
        int kk = blockIdx.x*4 + q;
        if (kk < K2N) g_Yk2[kk*800 + io] = make_float2(acc[q].x*sc, acc[q].y*sc);
    }
}

// Z2, Hermitian-halved: Z[-m,-n] = (-1)^{m+n} conj(Z[m,n]).
template<int L>
__global__ void kZ2(){
    const int l = (L - 1) / 2;
    const int base = c_SQ[l];
    const int NH = l + 1;
    int b = blockIdx.x, tid = threadIdx.x;
    __shared__ float2 A[L*L*20];
    for (int idx = tid; idx < L*L*20; idx += 256){
        int m = idx / (L*20), r = idx % (L*20), kk = r / 20, i = r % 20;
        A[idx] = g_X2[(base + m*L + kk)*BI2 + b*20 + i];
    }
    __syncthreads();
    for (int p = tid; p < NH*40; p += 256){
        int q = p / 40, o = p % 40;
        int n0 = l + q;
        float2 acc[L];
        #pragma unroll
        for (int m = 0; m < L; m++) acc[m] = make_float2(0.f, 0.f);
        for (int kk = 0; kk < L; kk++){
            const float2* Yrow = &g_Yk2[(base + n0*L + kk)*800 + o];
            #pragma unroll 4
            for (int i = 0; i < 20; i++){
                float2 y = Yrow[i*40];
                #pragma unroll
                for (int m = 0; m < L; m++){
                    float2 a = A[m*L*20 + kk*20 + i];
                    acc[m].x += a.x*y.x - a.y*y.y;
                    acc[m].y += a.x*y.y + a.y*y.x;
                }
            }
        }
        #pragma unroll
        for (int m = 0; m < L; m++){
            g_Z2[(base + m*L + n0)*5120 + b*40 + o] = acc[m];
            if (q > 0){
                float sgn = ((m + n0) & 1) ? -1.f : 1.f;
                g_Z2[(base + (2*l - m)*L + (2*l - n0))*5120 + b*40 + o] =
                    make_float2(sgn*acc[m].x, -sgn*acc[m].y);
            }
        }
    }
}

// Fused layer-2 synthesis + relu + quadrature + feature; 2 j per iteration.
__global__ void kSynth2(){
    __shared__ float2 ZL[286], E2[132], G2s[2][121], H2[2][72];
    __shared__ float  red[128];
    int o = blockIdx.x, b = blockIdx.y, tid = threadIdx.x;
    for (int t = tid; t < 286; t += 128) ZL[t] = g_Z2[t*5120 + b*40 + o];
    for (int p = tid; p < 132; p += 128) E2[p] = g_E2[p];
    __syncthreads();
    float facc = 0.f;
    for (int jj = 0; jj < 6; jj++){
        int j0 = 2*jj;
        for (int p = tid; p < 122; p += 128){
            int j2 = p / 61, pp = p % 61;
            int m = pp/11 - 5, n = pp%11 - 5;
            int lmin = max(abs(m), abs(n));
            float2 acc = make_float2(0.f, 0.f);
            const float* dt = &g_d2tab[((j0 + j2)*121 + pp)*6];
            for (int l = lmin; l < 6; l++){
                int Ls = 2*l + 1;
                float2 z = ZL[c_SQ[l] + (m + l)*Ls + (n + l)];
                float d = dt[l];
                acc.x += d * z.x; acc.y += d * z.y;
            }
            G2s[j2][pp] = acc;
            G2s[j2][120 - pp] = make_float2(acc.x, -acc.y);
        }
        __syncthreads();
        for (int p = tid; p < 144; p += 128){
            int j2 = p / 72, q = p % 72;
            int mi = q / 12, a3 = q % 12;
            float2 acc = make_float2(0.f, 0.f);
            #pragma unroll
            for (int ni = 0; ni < 11; ni++){
                float2 g = G2s[j2][mi*11 + ni], e = E2[ni*12 + a3];
                acc.x += g.x*e.x - g.y*e.y;
                acc.y += g.x*e.y + g.y*e.x;
            }
            H2[j2][q] = acc;
        }
        __syncthreads();
        for (int p = tid; p < 288; p += 128){
            int j2 = p / 144, q = p % 144;
            int a2 = q / 12, a3 = q % 12;
            float v = H2[j2][5*12 + a3].x;
            #pragma unroll
            for (int mi = 0; mi < 5; mi++){
                float2 h = H2[j2][mi*12 + a3], e = E2[mi*12 + a2];
                v += 2.f * (h.x*e.x - h.y*e.y);
            }
            facc += g_w2j[j0 + j2] * fmaxf(v, 0.f);
        }
        __syncthreads();
    }
    red[tid] = facc;
    __syncthreads();
    for (int s = 64; s > 0; s >>= 1){
        if (tid < s) red[tid] += red[tid + s];
        __syncthreads();
    }
    if (tid == 0){
        const float INTEG = (float)((TWOPI_D/12.0)*(TWOPI_D/12.0));
        g_feat[b*40 + o] = INTEG * red[0];
    }
}

__global__ void kOut(const float* __restrict__ wout, const float* __restrict__ bias,
                     float* __restrict__ out){
    int g = blockIdx.x*128 + threadIdx.x;
    if (g >= 1280) return;
    int b = g / 10, fo = g % 10;
    float s = bias[fo];
    #pragma unroll
    for (int o = 0; o < 40; o++) s += g_feat[b*40 + o] * wout[fo*40 + o];
    out[g] = s;
}

// ---------------------------------------------------------------------------
extern "C" void kernel_launch(void* const* d_in, const int* in_sizes, int n_in,
                              void* d_out, int out_size){
    (void)in_sizes; (void)n_in; (void)out_size;
    const float* x  = (const float*)d_in[0];
    const float* k1 = (const float*)d_in[1];
    const float* k2 = (const float*)d_in[2];
    const float* wo = (const float*)d_in[3];
    const float* bo = (const float*)d_in[4];
    float* out = (float*)d_out;

    static int smem_set = 0;
    if (!smem_set){
        cudaFuncSetAttribute(kSynth1, cudaFuncAttributeMaxDynamicSharedMemorySize, SMEM1_BYTES);
        smem_set = 1;
    }

    kRawAll <<<146, 256>>>();
    kAsmAll <<<588, 256>>>();

    kDFT1  <<<120, 256>>>(x);
    kX1    <<<100, 128>>>();
    kYk1   <<<20, 128>>>(k1);
    kK2T   <<<1200, 128>>>(k2);
    kYk2   <<<dim3(72, 7), 128>>>();
    kSynth1<<<dim3(20, 128), 256, SMEM1_BYTES>>>();

    kZ2<1> <<<128, 256>>>();
    kZ2<3> <<<128, 256>>>();
    kZ2<5> <<<128, 256>>>();
    kZ2<7> <<<128, 256>>>();
    kZ2<9> <<<128, 256>>>();
    kZ2<11><<<128, 256>>>();

    kSynth2<<<dim3(40, 128), 128>>>();
    kOut   <<<10, 128>>>(wo, bo, out);
}